// round 5
// baseline (speedup 1.0000x reference)
#include <cuda_runtime.h>

// Stochastic LIF neuron scan — R4.
// Inputs (metadata order): x [B,T,N] f32, noise [B,T,N] f32, unif [B,T,N] f32.
// Output: spikes [B,T,N] f32.
//
// Per (b,n):  u=0
//   u = 0.5*u + x_t        (separate mul+add, NO fma — matches JAX rounding)
//   u = u - noise_t
//   v = u - 1
//   q = (v + 0.4) / 0.8    (IEEE f32 division; clip removed — provably
//                           bit-identical since unif ∈ [0,1))
//   o = (unif_t < q) ? 1 : 0
//   u = o ? 0 : u
//
// HBM-bound one-pass stream (536 MB). float4 over n. R4 changes:
//   - __launch_bounds__(256, 6): cap regs -> 6 blocks/SM, 48 warps, fewer
//     quantized waves, more outstanding loads chip-wide.
//   - __ldcs/__stcs streaming hints (touch-once data, evict-first).
//   - clip removed (reg + instr diet; bit-exact as argued above).

#define B_DIM 32
#define T_DIM 16
#define N_DIM 65536
#define N4    (N_DIM / 4)   // 16384 float4 per (b,t) row

__global__ __launch_bounds__(256, 6)
void neuron_scan_kernel(const float4* __restrict__ x,
                        const float4* __restrict__ noise,
                        const float4* __restrict__ unif,
                        float4* __restrict__ out)
{
    int tid = blockIdx.x * blockDim.x + threadIdx.x;   // 0 .. B*N4-1
    if (tid >= B_DIM * N4) return;

    int b  = tid >> 14;          // tid / N4
    int n4 = tid & (N4 - 1);     // tid % N4

    // element-of-float4 index of (b, t=0, n4)
    int idx = b * (T_DIM * N4) + n4;

    float u0 = 0.0f, u1 = 0.0f, u2 = 0.0f, u3 = 0.0f;

    #pragma unroll 4
    for (int t = 0; t < T_DIM; ++t) {
        float4 xv = __ldcs(&x[idx]);
        float4 nv = __ldcs(&noise[idx]);
        float4 rv = __ldcs(&unif[idx]);

        float4 ov;

        // lane 0
        {
            float u = __fadd_rn(__fmul_rn(0.5f, u0), xv.x);
            u = __fsub_rn(u, nv.x);
            float v = __fsub_rn(u, 1.0f);
            float q = __fdiv_rn(__fadd_rn(v, 0.4f), 0.8f);
            bool  s = (rv.x < q);
            ov.x = s ? 1.0f : 0.0f;
            u0   = s ? 0.0f : u;
        }
        // lane 1
        {
            float u = __fadd_rn(__fmul_rn(0.5f, u1), xv.y);
            u = __fsub_rn(u, nv.y);
            float v = __fsub_rn(u, 1.0f);
            float q = __fdiv_rn(__fadd_rn(v, 0.4f), 0.8f);
            bool  s = (rv.y < q);
            ov.y = s ? 1.0f : 0.0f;
            u1   = s ? 0.0f : u;
        }
        // lane 2
        {
            float u = __fadd_rn(__fmul_rn(0.5f, u2), xv.z);
            u = __fsub_rn(u, nv.z);
            float v = __fsub_rn(u, 1.0f);
            float q = __fdiv_rn(__fadd_rn(v, 0.4f), 0.8f);
            bool  s = (rv.z < q);
            ov.z = s ? 1.0f : 0.0f;
            u2   = s ? 0.0f : u;
        }
        // lane 3
        {
            float u = __fadd_rn(__fmul_rn(0.5f, u3), xv.w);
            u = __fsub_rn(u, nv.w);
            float v = __fsub_rn(u, 1.0f);
            float q = __fdiv_rn(__fadd_rn(v, 0.4f), 0.8f);
            bool  s = (rv.w < q);
            ov.w = s ? 1.0f : 0.0f;
            u3   = s ? 0.0f : u;
        }

        __stcs(&out[idx], ov);
        idx += N4;   // next timestep, same (b, n4)
    }
}

extern "C" void kernel_launch(void* const* d_in, const int* in_sizes, int n_in,
                              void* d_out, int out_size)
{
    const float4* x     = (const float4*)d_in[0];
    const float4* noise = (const float4*)d_in[1];
    const float4* unif  = (const float4*)d_in[2];
    float4* out         = (float4*)d_out;

    const int total_threads = B_DIM * N4;          // 524288
    const int block = 256;
    const int grid  = (total_threads + block - 1) / block;   // 2048

    neuron_scan_kernel<<<grid, block>>>(x, noise, unif, out);
}

// round 6
// speedup vs baseline: 1.0256x; 1.0256x over previous
#include <cuda_runtime.h>

// Stochastic LIF neuron scan — R5.
// Inputs (metadata order): x [B,T,N] f32, noise [B,T,N] f32, unif [B,T,N] f32.
// Output: spikes [B,T,N] f32.
//
// Per (b,n):  u=0
//   u = 0.5*u + x_t        (separate mul+add, NO fma — matches JAX rounding)
//   u = u - noise_t
//   v = u - 1
//   q = (v + 0.4) / 0.8    (IEEE f32 division; clip removed — bit-identical
//                           since unif ∈ [0,1): unif<min(q,1) ⟺ unif<q and
//                           unif<max(q,0) ⟺ unif<q)
//   o = (unif_t < q) ? 1 : 0
//   u = o ? 0 : u
//
// R5 = R3 memory behavior (default cached loads/stores, no occupancy clamp —
// both R4 "optimizations" measurably hurt DRAM throughput) + the clip-free
// spike math kept from R4 (harmless instruction diet).

#define B_DIM 32
#define T_DIM 16
#define N_DIM 65536
#define N4    (N_DIM / 4)   // 16384 float4 per (b,t) row

__global__ __launch_bounds__(256)
void neuron_scan_kernel(const float4* __restrict__ x,
                        const float4* __restrict__ noise,
                        const float4* __restrict__ unif,
                        float4* __restrict__ out)
{
    int tid = blockIdx.x * blockDim.x + threadIdx.x;   // 0 .. B*N4-1
    if (tid >= B_DIM * N4) return;

    int b  = tid >> 14;          // tid / N4
    int n4 = tid & (N4 - 1);     // tid % N4

    // element-of-float4 index of (b, t=0, n4)
    int idx = b * (T_DIM * N4) + n4;

    float u0 = 0.0f, u1 = 0.0f, u2 = 0.0f, u3 = 0.0f;

    #pragma unroll 4
    for (int t = 0; t < T_DIM; ++t) {
        float4 xv = x[idx];
        float4 nv = noise[idx];
        float4 rv = unif[idx];

        float4 ov;

        // lane 0
        {
            float u = __fadd_rn(__fmul_rn(0.5f, u0), xv.x);
            u = __fsub_rn(u, nv.x);
            float v = __fsub_rn(u, 1.0f);
            float q = __fdiv_rn(__fadd_rn(v, 0.4f), 0.8f);
            bool  s = (rv.x < q);
            ov.x = s ? 1.0f : 0.0f;
            u0   = s ? 0.0f : u;
        }
        // lane 1
        {
            float u = __fadd_rn(__fmul_rn(0.5f, u1), xv.y);
            u = __fsub_rn(u, nv.y);
            float v = __fsub_rn(u, 1.0f);
            float q = __fdiv_rn(__fadd_rn(v, 0.4f), 0.8f);
            bool  s = (rv.y < q);
            ov.y = s ? 1.0f : 0.0f;
            u1   = s ? 0.0f : u;
        }
        // lane 2
        {
            float u = __fadd_rn(__fmul_rn(0.5f, u2), xv.z);
            u = __fsub_rn(u, nv.z);
            float v = __fsub_rn(u, 1.0f);
            float q = __fdiv_rn(__fadd_rn(v, 0.4f), 0.8f);
            bool  s = (rv.z < q);
            ov.z = s ? 1.0f : 0.0f;
            u2   = s ? 0.0f : u;
        }
        // lane 3
        {
            float u = __fadd_rn(__fmul_rn(0.5f, u3), xv.w);
            u = __fsub_rn(u, nv.w);
            float v = __fsub_rn(u, 1.0f);
            float q = __fdiv_rn(__fadd_rn(v, 0.4f), 0.8f);
            bool  s = (rv.w < q);
            ov.w = s ? 1.0f : 0.0f;
            u3   = s ? 0.0f : u;
        }

        out[idx] = ov;
        idx += N4;   // next timestep, same (b, n4)
    }
}

extern "C" void kernel_launch(void* const* d_in, const int* in_sizes, int n_in,
                              void* d_out, int out_size)
{
    const float4* x     = (const float4*)d_in[0];
    const float4* noise = (const float4*)d_in[1];
    const float4* unif  = (const float4*)d_in[2];
    float4* out         = (float4*)d_out;

    const int total_threads = B_DIM * N4;          // 524288
    const int block = 256;
    const int grid  = (total_threads + block - 1) / block;   // 2048

    neuron_scan_kernel<<<grid, block>>>(x, noise, unif, out);
}